// round 3
// baseline (speedup 1.0000x reference)
#include <cuda_runtime.h>
#include <mma.h>
using namespace nvcuda;

#define NN 10000
#define NNP 10112          // padded to multiple of 128 for guard-free GEMM stores
#define NE 100000
#define NET (NE + NN)
#define FD 768
#define HH 6
#define CH 128
#define BGR 64
#define OC 128

// ---------------- scratch (device globals: allocation-free) ----------------
__device__ float g_hx[(size_t)NNP * FD];
__device__ float g_y[(size_t)NNP * FD];
__device__ float g_as[NN * HH];
__device__ float g_ad[NN * HH];
__device__ int   g_deg[NN];
__device__ int   g_ptr[NN + 1];
__device__ int   g_cur[NN];
__device__ int   g_csr[NET];
__device__ float g_colsum[FD];
__device__ float g_colsum2[FD];
__device__ float g_scale[FD];
__device__ float g_shift[FD];
__device__ float g_lin[(size_t)NNP * OC];

// monotone float<->uint encoding for atomicMax on floats
__device__ __forceinline__ unsigned fenc(float f) {
    unsigned u = __float_as_uint(f);
    return (u & 0x80000000u) ? ~u : (u | 0x80000000u);
}
__device__ __forceinline__ float fdec(unsigned u) {
    return (u & 0x80000000u) ? __uint_as_float(u ^ 0x80000000u)
                             : __uint_as_float(~u);
}
#define ENC_NEG_INF 0x007FFFFFu  // fenc(-inf)

// ---------------- CSR build ----------------
__global__ void k_zero_deg() {
    int i = blockIdx.x * blockDim.x + threadIdx.x;
    if (i < NN) g_deg[i] = 0;
}

__global__ void k_count(const int* __restrict__ adj) {
    int i = blockIdx.x * blockDim.x + threadIdx.x;
    if (i >= NET) return;
    int d = (i < NE) ? adj[NE + i] : (i - NE);
    atomicAdd(&g_deg[d], 1);
}

__global__ void k_scan() {
    __shared__ int sh[1024];
    __shared__ int soff;
    int t = threadIdx.x;
    if (t == 0) soff = 0;
    __syncthreads();
    for (int base = 0; base < NN; base += 1024) {
        int v = (base + t < NN) ? g_deg[base + t] : 0;
        sh[t] = v;
        __syncthreads();
        for (int d = 1; d < 1024; d <<= 1) {
            int y = (t >= d) ? sh[t - d] : 0;
            __syncthreads();
            sh[t] += y;
            __syncthreads();
        }
        int off = soff;
        if (base + t < NN) {
            int ex = off + sh[t] - v;
            g_ptr[base + t] = ex;
            g_cur[base + t] = ex;
        }
        __syncthreads();
        if (t == 1023) soff = off + sh[1023];
        __syncthreads();
    }
    if (t == 0) g_ptr[NN] = soff;
}

__global__ void k_scatter(const int* __restrict__ adj) {
    int i = blockIdx.x * blockDim.x + threadIdx.x;
    if (i >= NET) return;
    int s, d;
    if (i < NE) { s = adj[i]; d = adj[NE + i]; }
    else        { s = i - NE; d = i - NE; }
    int pos = atomicAdd(&g_cur[d], 1);
    g_csr[pos] = s;
}

// ---------------- tensor-core GEMM (3xTF32): C[M,Nc] = A'[M,K] @ B[K,Nc]
// A' = A * ascale[col] + ashift[col] (fused BN) when ascale != nullptr.
// Block tile 128x128, K-step 32, 8 warps (warp tile 32x64 = 2x4 wmma 16x16).
// M padded: stores are unguarded (C buffers are NNP rows); A loads guarded by M.
__global__ __launch_bounds__(256) void k_gemm_tc(
    const float* __restrict__ A, const float* __restrict__ B,
    const float* __restrict__ ascale, const float* __restrict__ ashift,
    float* __restrict__ C, int M, int Nc, int K)
{
    __shared__ float As[128][33];
    __shared__ float Bs[32][132];
    const int t = threadIdx.x;
    const int bm = blockIdx.y, bn = blockIdx.x;
    const int warp = t >> 5;
    const int warp_m = warp & 3;   // 0..3 -> 32-row stripes
    const int warp_n = warp >> 2;  // 0..1 -> 64-col stripes

    typedef wmma::fragment<wmma::matrix_a, 16, 16, 8, wmma::precision::tf32, wmma::row_major> FragA;
    typedef wmma::fragment<wmma::matrix_b, 16, 16, 8, wmma::precision::tf32, wmma::row_major> FragB;
    typedef wmma::fragment<wmma::accumulator, 16, 16, 8, float> FragC;

    FragC acc[2][4];
#pragma unroll
    for (int i = 0; i < 2; i++)
#pragma unroll
        for (int j = 0; j < 4; j++) wmma::fill_fragment(acc[i][j], 0.0f);

    const bool fuse = (ascale != nullptr);

    for (int k0 = 0; k0 < K; k0 += 32) {
        // load A tile 128x32
#pragma unroll
        for (int p = 0; p < 4; p++) {
            int idx = t + p * 256;
            int r = idx >> 3, c4 = (idx & 7) * 4;
            int grow = bm * 128 + r;
            float4 v = make_float4(0.f, 0.f, 0.f, 0.f);
            if (grow < M)
                v = *(const float4*)(A + (size_t)grow * K + k0 + c4);
            if (fuse) {
                float4 s  = *(const float4*)(ascale + k0 + c4);
                float4 sh = *(const float4*)(ashift + k0 + c4);
                if (grow < M) {
                    v.x = v.x * s.x + sh.x;
                    v.y = v.y * s.y + sh.y;
                    v.z = v.z * s.z + sh.z;
                    v.w = v.w * s.w + sh.w;
                }
            }
            As[r][c4 + 0] = v.x;
            As[r][c4 + 1] = v.y;
            As[r][c4 + 2] = v.z;
            As[r][c4 + 3] = v.w;
        }
        // load B tile 32x128
#pragma unroll
        for (int p = 0; p < 4; p++) {
            int idx = t + p * 256;
            int r = idx >> 5, c4 = (idx & 31) * 4;
            float4 v = *(const float4*)(B + (size_t)(k0 + r) * Nc + bn * 128 + c4);
            Bs[r][c4 + 0] = v.x;
            Bs[r][c4 + 1] = v.y;
            Bs[r][c4 + 2] = v.z;
            Bs[r][c4 + 3] = v.w;
        }
        __syncthreads();

#pragma unroll
        for (int k8 = 0; k8 < 4; k8++) {
            FragA ah[2], al[2];
#pragma unroll
            for (int i = 0; i < 2; i++) {
                FragA af;
                wmma::load_matrix_sync(af, &As[warp_m * 32 + i * 16][k8 * 8], 33);
#pragma unroll
                for (int e = 0; e < af.num_elements; e++) {
                    float v = af.x[e];
                    float hi = wmma::__float_to_tf32(v);
                    ah[i].x[e] = hi;
                    al[i].x[e] = wmma::__float_to_tf32(v - hi);
                }
            }
#pragma unroll
            for (int j = 0; j < 4; j++) {
                FragB bf, bh, bl;
                wmma::load_matrix_sync(bf, &Bs[k8 * 8][warp_n * 64 + j * 16], 132);
#pragma unroll
                for (int e = 0; e < bf.num_elements; e++) {
                    float v = bf.x[e];
                    float hi = wmma::__float_to_tf32(v);
                    bh.x[e] = hi;
                    bl.x[e] = wmma::__float_to_tf32(v - hi);
                }
#pragma unroll
                for (int i = 0; i < 2; i++) {
                    wmma::mma_sync(acc[i][j], ah[i], bh, acc[i][j]);
                    wmma::mma_sync(acc[i][j], al[i], bh, acc[i][j]);
                    wmma::mma_sync(acc[i][j], ah[i], bl, acc[i][j]);
                }
            }
        }
        __syncthreads();
    }

    // unguarded stores: C has NNP (multiple of 128) rows
#pragma unroll
    for (int i = 0; i < 2; i++) {
#pragma unroll
        for (int j = 0; j < 4; j++) {
            int r = bm * 128 + warp_m * 32 + i * 16;
            int c = bn * 128 + warp_n * 64 + j * 16;
            wmma::store_matrix_sync(C + (size_t)r * Nc + c, acc[i][j], Nc, wmma::mem_row_major);
        }
    }
}

// ---------------- attention scores: as/ad[n,h] = <hx[n,h,:], att[h,:]> ----------------
__global__ __launch_bounds__(256) void k_att(
    const float* __restrict__ hx, const float* __restrict__ atts,
    const float* __restrict__ attd)
{
    int gt = blockIdx.x * blockDim.x + threadIdx.x;
    int w = gt >> 5, lane = gt & 31;
    if (w >= NN * HH) return;
    int n = w / HH, h = w - n * HH;
    const float* row = hx + (size_t)n * FD + h * CH;
    const float* vs = atts + h * CH;
    const float* vd = attd + h * CH;
    float sa = 0.f, sd = 0.f;
#pragma unroll
    for (int c = lane; c < CH; c += 32) {
        float v = row[c];
        sa += v * vs[c];
        sd += v * vd[c];
    }
#pragma unroll
    for (int o = 16; o; o >>= 1) {
        sa += __shfl_down_sync(0xffffffffu, sa, o);
        sd += __shfl_down_sync(0xffffffffu, sd, o);
    }
    if (lane == 0) { g_as[w] = sa; g_ad[w] = sd; }
}

// ---------------- fused softmax + aggregate + bias + relu, per dst node ----------------
__global__ __launch_bounds__(256) void k_agg(
    const float* __restrict__ hx, const float* __restrict__ bias,
    float* __restrict__ out)
{
    int d = blockIdx.x;
    int t = threadIdx.x;
    __shared__ float    s_ad[HH];
    __shared__ unsigned s_m[HH];
    __shared__ float    s_mf[HH];
    __shared__ float    s_s[HH];
    __shared__ float    s_w[128 * HH];
    __shared__ int      s_src[128];

    int p0 = g_ptr[d], p1 = g_ptr[d + 1];
    int deg = p1 - p0;
    if (t < HH) {
        s_ad[t] = g_ad[d * HH + t];
        s_m[t] = ENC_NEG_INF;
        s_s[t] = 0.f;
    }
    __syncthreads();

    float lm[HH];
#pragma unroll
    for (int h = 0; h < HH; h++) lm[h] = -3.0e38f;
    for (int i = t; i < deg; i += 256) {
        int s = g_csr[p0 + i];
#pragma unroll
        for (int h = 0; h < HH; h++) {
            float e = g_as[s * HH + h] + s_ad[h];
            e = (e > 0.f) ? e : 0.2f * e;
            lm[h] = fmaxf(lm[h], e);
        }
    }
#pragma unroll
    for (int h = 0; h < HH; h++) atomicMax(&s_m[h], fenc(lm[h]));
    __syncthreads();
    if (t < HH) s_mf[t] = fdec(s_m[t]);
    __syncthreads();

    float a0 = 0.f, a1 = 0.f, a2 = 0.f;
    int c0 = t, c1 = t + 256, c2 = t + 512;
    int h0 = c0 >> 7, h1 = c1 >> 7, h2 = c2 >> 7;
    for (int cb = 0; cb < deg; cb += 128) {
        int cl = min(128, deg - cb);
        for (int j = t; j < cl * HH; j += 256) {
            int i = j / HH, h = j - i * HH;
            int s = g_csr[p0 + cb + i];
            if (h == 0) s_src[i] = s;
            float e = g_as[s * HH + h] + s_ad[h];
            e = (e > 0.f) ? e : 0.2f * e;
            float w = __expf(e - s_mf[h]);
            s_w[i * HH + h] = w;
            atomicAdd(&s_s[h], w);
        }
        __syncthreads();
        for (int i = 0; i < cl; i++) {
            const float* row = hx + (size_t)s_src[i] * FD;
            a0 += s_w[i * HH + h0] * row[c0];
            a1 += s_w[i * HH + h1] * row[c1];
            a2 += s_w[i * HH + h2] * row[c2];
        }
        __syncthreads();
    }

    float r0 = a0 / s_s[h0] + bias[c0];
    float r1 = a1 / s_s[h1] + bias[c1];
    float r2 = a2 / s_s[h2] + bias[c2];
    size_t base = (size_t)d * FD;
    out[base + c0] = fmaxf(r0, 0.f);
    out[base + c1] = fmaxf(r1, 0.f);
    out[base + c2] = fmaxf(r2, 0.f);
}

// ---------------- batch norm stats (apply is fused into next GEMM) ----------------
__global__ void k_zero_cols() {
    int i = blockIdx.x * blockDim.x + threadIdx.x;
    if (i < FD) { g_colsum[i] = 0.f; g_colsum2[i] = 0.f; }
}

__global__ __launch_bounds__(256) void k_bn_stats(const float* __restrict__ y) {
    int b = blockIdx.x;
    int rows_per = (NN + gridDim.x - 1) / gridDim.x;
    int r0 = b * rows_per;
    int r1 = min(NN, r0 + rows_per);
    int t = threadIdx.x;
    float s[3] = {0.f, 0.f, 0.f}, q[3] = {0.f, 0.f, 0.f};
    for (int r = r0; r < r1; r++) {
        const float* row = y + (size_t)r * FD;
#pragma unroll
        for (int k = 0; k < 3; k++) {
            float v = row[t + k * 256];
            s[k] += v;
            q[k] += v * v;
        }
    }
#pragma unroll
    for (int k = 0; k < 3; k++) {
        atomicAdd(&g_colsum[t + k * 256], s[k]);
        atomicAdd(&g_colsum2[t + k * 256], q[k]);
    }
}

__global__ void k_bn_fin(const float* __restrict__ g, const float* __restrict__ be) {
    int c = blockIdx.x * blockDim.x + threadIdx.x;
    if (c >= FD) return;
    float mu = g_colsum[c] * (1.0f / NN);
    float var = g_colsum2[c] * (1.0f / NN) - mu * mu;
    float sc = g[c] * rsqrtf(var + 1e-5f);
    g_scale[c] = sc;
    g_shift[c] = be[c] - mu * sc;
}

// ---------------- global max pool over graphs (bias fused here) ----------------
__global__ void k_pool_init(unsigned* __restrict__ out) {
    int i = blockIdx.x * blockDim.x + threadIdx.x;
    if (i < BGR * OC) out[i] = ENC_NEG_INF;
}

__global__ void k_pool(const int* __restrict__ ibatch, const float* __restrict__ lb,
                       unsigned* __restrict__ out) {
    int i = blockIdx.x * blockDim.x + threadIdx.x;
    if (i >= NN * OC) return;
    int n = i / OC, c = i - n * OC;
    int g = ibatch[n];
    atomicMax(&out[g * OC + c], fenc(g_lin[i] + lb[c]));
}

__global__ void k_pool_dec(float* __restrict__ out) {
    int i = blockIdx.x * blockDim.x + threadIdx.x;
    if (i < BGR * OC) {
        unsigned u = ((unsigned*)out)[i];
        out[i] = fdec(u);
    }
}

// ---------------- launch ----------------
extern "C" void kernel_launch(void* const* d_in, const int* in_sizes, int n_in,
                              void* d_out, int out_size) {
    const float* x   = (const float*)d_in[0];
    const int*   adj = (const int*)d_in[1];
    const int*   ib  = (const int*)d_in[2];
    const float* W1  = (const float*)d_in[3];
    const float* as1 = (const float*)d_in[4];
    const float* ad1 = (const float*)d_in[5];
    const float* b1  = (const float*)d_in[6];
    const float* g1  = (const float*)d_in[7];
    const float* be1 = (const float*)d_in[8];
    const float* W2  = (const float*)d_in[9];
    const float* as2 = (const float*)d_in[10];
    const float* ad2 = (const float*)d_in[11];
    const float* b2  = (const float*)d_in[12];
    const float* g2  = (const float*)d_in[13];
    const float* be2 = (const float*)d_in[14];
    const float* lW  = (const float*)d_in[15];
    const float* lb  = (const float*)d_in[16];

    float *hx, *y, *lin, *scale, *shift;
    cudaGetSymbolAddress((void**)&hx, g_hx);
    cudaGetSymbolAddress((void**)&y, g_y);
    cudaGetSymbolAddress((void**)&lin, g_lin);
    cudaGetSymbolAddress((void**)&scale, g_scale);
    cudaGetSymbolAddress((void**)&shift, g_shift);

    // CSR build
    k_zero_deg<<<(NN + 255) / 256, 256>>>();
    k_count<<<(NET + 255) / 256, 256>>>(adj);
    k_scan<<<1, 1024>>>();
    k_scatter<<<(NET + 255) / 256, 256>>>(adj);

    dim3 gemm_grid(FD / 128, NNP / 128);

    // layer 1
    k_gemm_tc<<<gemm_grid, 256>>>(x, W1, nullptr, nullptr, hx, NN, FD, 256);
    k_att<<<(NN * HH * 32 + 255) / 256, 256>>>(hx, as1, ad1);
    k_agg<<<NN, 256>>>(hx, b1, y);
    k_zero_cols<<<3, 256>>>();
    k_bn_stats<<<80, 256>>>(y);
    k_bn_fin<<<3, 256>>>(g1, be1);

    // layer 2 (BN1 apply fused into A-load)
    k_gemm_tc<<<gemm_grid, 256>>>(y, W2, scale, shift, hx, NN, FD, FD);
    k_att<<<(NN * HH * 32 + 255) / 256, 256>>>(hx, as2, ad2);
    k_agg<<<NN, 256>>>(hx, b2, y);
    k_zero_cols<<<3, 256>>>();
    k_bn_stats<<<80, 256>>>(y);
    k_bn_fin<<<3, 256>>>(g2, be2);

    // linear head (BN2 apply fused into A-load)
    dim3 lin_grid(OC / 128, NNP / 128);
    k_gemm_tc<<<lin_grid, 256>>>(y, lW, scale, shift, lin, NN, OC, FD);

    // pooling (lin bias fused here)
    k_pool_init<<<(BGR * OC + 255) / 256, 256>>>((unsigned*)d_out);
    k_pool<<<(NN * OC + 255) / 256, 256>>>(ib, lb, (unsigned*)d_out);
    k_pool_dec<<<(BGR * OC + 255) / 256, 256>>>((float*)d_out);
}

// round 5
// speedup vs baseline: 2.7159x; 2.7159x over previous
#include <cuda_runtime.h>
#include <cuda_bf16.h>
#include <cstdint>

#define NN 10000
#define NNP 10112          // padded to multiple of 128 for guard-free GEMM
#define NE 100000
#define NET (NE + NN)
#define FD 768
#define HH 6
#define CH 128
#define BGR 64
#define OC 128

// ---------------- scratch (device globals: allocation-free) ----------------
__device__ float g_hx[(size_t)NNP * FD];
__device__ float g_y[(size_t)NNP * FD];
__device__ float g_as[NN * HH];
__device__ float g_ad[NN * HH];
__device__ int   g_deg[NN];
__device__ int   g_ptr[NN + 1];
__device__ int   g_cur[NN];
__device__ int   g_csr[NET];
__device__ float g_colsum[FD];
__device__ float g_colsum2[FD];
__device__ float g_scale[FD];
__device__ float g_shift[FD];
__device__ float g_lin[(size_t)NNP * OC];
__device__ __nv_bfloat16 g_bt_hi[(size_t)FD * FD];   // W^T split: [N][K]
__device__ __nv_bfloat16 g_bt_lo[(size_t)FD * FD];
__device__ __nv_bfloat16 g_a_hi[(size_t)NNP * FD];   // A split: [NNP][K]
__device__ __nv_bfloat16 g_a_lo[(size_t)NNP * FD];

// monotone float<->uint encoding for atomicMax on floats
__device__ __forceinline__ unsigned fenc(float f) {
    unsigned u = __float_as_uint(f);
    return (u & 0x80000000u) ? ~u : (u | 0x80000000u);
}
__device__ __forceinline__ float fdec(unsigned u) {
    return (u & 0x80000000u) ? __uint_as_float(u ^ 0x80000000u)
                             : __uint_as_float(~u);
}
#define ENC_NEG_INF 0x007FFFFFu  // fenc(-inf)

// ---------------- PTX helpers (base sm_80+ features only) ----------------
__device__ __forceinline__ uint32_t smem_u32(const void* p) {
    uint32_t a;
    asm("{ .reg .u64 t; cvta.to.shared.u64 t, %1; cvt.u32.u64 %0, t; }" : "=r"(a) : "l"(p));
    return a;
}
#define SWZ(off) ((off) ^ (((off) >> 3) & 0x70))

__device__ __forceinline__ void cp16(uint32_t dst, const void* src) {
    asm volatile("cp.async.cg.shared.global [%0], [%1], 16;"
                 :: "r"(dst), "l"(__cvta_generic_to_global(src)) : "memory");
}
#define CP_COMMIT() asm volatile("cp.async.commit_group;" ::: "memory")
#define CP_WAIT1()  asm volatile("cp.async.wait_group 1;" ::: "memory")
#define CP_WAIT0()  asm volatile("cp.async.wait_group 0;" ::: "memory")

__device__ __forceinline__ void ldsm4(uint32_t* r, uint32_t addr) {
    asm volatile("ldmatrix.sync.aligned.m8n8.x4.shared.b16 {%0,%1,%2,%3}, [%4];"
                 : "=r"(r[0]), "=r"(r[1]), "=r"(r[2]), "=r"(r[3]) : "r"(addr));
}
__device__ __forceinline__ void mma16816(float* c, const uint32_t* a, const uint32_t* b) {
    asm volatile(
        "mma.sync.aligned.m16n8k16.row.col.f32.bf16.bf16.f32 "
        "{%0,%1,%2,%3}, {%4,%5,%6,%7}, {%8,%9}, {%0,%1,%2,%3};"
        : "+f"(c[0]), "+f"(c[1]), "+f"(c[2]), "+f"(c[3])
        : "r"(a[0]), "r"(a[1]), "r"(a[2]), "r"(a[3]), "r"(b[0]), "r"(b[1]));
}

// ---------------- CSR build ----------------
__global__ void k_zero_deg() {
    int i = blockIdx.x * blockDim.x + threadIdx.x;
    if (i < NN) g_deg[i] = 0;
}

__global__ void k_count(const int* __restrict__ adj) {
    int i = blockIdx.x * blockDim.x + threadIdx.x;
    if (i >= NET) return;
    int d = (i < NE) ? adj[NE + i] : (i - NE);
    atomicAdd(&g_deg[d], 1);
}

__global__ void k_scan() {
    __shared__ int sh[1024];
    __shared__ int soff;
    int t = threadIdx.x;
    if (t == 0) soff = 0;
    __syncthreads();
    for (int base = 0; base < NN; base += 1024) {
        int v = (base + t < NN) ? g_deg[base + t] : 0;
        sh[t] = v;
        __syncthreads();
        for (int d = 1; d < 1024; d <<= 1) {
            int y = (t >= d) ? sh[t - d] : 0;
            __syncthreads();
            sh[t] += y;
            __syncthreads();
        }
        int off = soff;
        if (base + t < NN) {
            int ex = off + sh[t] - v;
            g_ptr[base + t] = ex;
            g_cur[base + t] = ex;
        }
        __syncthreads();
        if (t == 1023) soff = off + sh[1023];
        __syncthreads();
    }
    if (t == 0) g_ptr[NN] = soff;
}

__global__ void k_scatter(const int* __restrict__ adj) {
    int i = blockIdx.x * blockDim.x + threadIdx.x;
    if (i >= NET) return;
    int s, d;
    if (i < NE) { s = adj[i]; d = adj[NE + i]; }
    else        { s = i - NE; d = i - NE; }
    int pos = atomicAdd(&g_cur[d], 1);
    g_csr[pos] = s;
}

// ---------------- weight prep: tiled transpose + bf16 hi/lo split ----------------
// W[K][N] -> g_bt_hi/lo[N][K]
__global__ void k_prep_w(const float* __restrict__ W, int K, int N) {
    __shared__ float tl[32][33];
    int n0 = blockIdx.x * 32, k0 = blockIdx.y * 32;
    int tx = threadIdx.x, ty = threadIdx.y;  // (32, 8)
    for (int r = ty; r < 32; r += 8)
        tl[r][tx] = W[(size_t)(k0 + r) * N + n0 + tx];
    __syncthreads();
    for (int r = ty; r < 32; r += 8) {
        float v = tl[tx][r];                 // W[k0+tx][n0+r]
        int n = n0 + r, k = k0 + tx;
        __nv_bfloat16 h = __float2bfloat16(v);
        g_bt_hi[(size_t)n * K + k] = h;
        g_bt_lo[(size_t)n * K + k] = __float2bfloat16(v - __bfloat162float(h));
    }
}

// ---------------- A prep: (optional BN) + bf16 hi/lo split ----------------
// src fp32 [.. x K] -> g_a_hi/lo [NNP][K]; rows >= NN zero-filled.
__global__ void k_split(const float* __restrict__ src,
                        const float* __restrict__ scale, const float* __restrict__ shift,
                        int K) {
    int i = blockIdx.x * blockDim.x + threadIdx.x;  // over NNP*K/4
    if (i >= NNP * (K / 4)) return;
    int r = i / (K / 4), c4 = (i % (K / 4)) * 4;
    float4 v = make_float4(0.f, 0.f, 0.f, 0.f);
    if (r < NN) {
        v = *(const float4*)(src + (size_t)r * K + c4);
        if (scale) {
            float4 s = *(const float4*)(scale + c4);
            float4 h = *(const float4*)(shift + c4);
            v.x = v.x * s.x + h.x; v.y = v.y * s.y + h.y;
            v.z = v.z * s.z + h.z; v.w = v.w * s.w + h.w;
        }
    }
    float in[4] = {v.x, v.y, v.z, v.w};
    uint32_t hi[2], lo[2];
#pragma unroll
    for (int q = 0; q < 2; q++) {
        float a = in[2 * q], b = in[2 * q + 1];
        __nv_bfloat16 ha = __float2bfloat16(a), hb = __float2bfloat16(b);
        __nv_bfloat162 hp; hp.x = ha; hp.y = hb;
        __nv_bfloat16 la = __float2bfloat16(a - __bfloat162float(ha));
        __nv_bfloat16 lb = __float2bfloat16(b - __bfloat162float(hb));
        __nv_bfloat162 lp; lp.x = la; lp.y = lb;
        hi[q] = *(uint32_t*)&hp;
        lo[q] = *(uint32_t*)&lp;
    }
    *(uint2*)(g_a_hi + (size_t)r * K + c4) = make_uint2(hi[0], hi[1]);
    *(uint2*)(g_a_lo + (size_t)r * K + c4) = make_uint2(lo[0], lo[1]);
}

// ---------------- HMMA GEMM: C[NNP,Nc] = (a_hi+a_lo) @ (bt_hi+bt_lo)^T ------
// split product: AhBh + AhBl + AlBh (fp32 accum). CTA tile 128x128, k-chunk 64,
// 2-stage cp.async pipeline. 8 warps, warp tile 32x64.
#define STG 65536          // per-stage smem: Ahi|Alo|Bhi|Blo 16KB each
#define SM_GEMM (2 * STG)

__global__ __launch_bounds__(256) void k_gemm_mma(float* __restrict__ C, int Nc, int K) {
    extern __shared__ __align__(16) char sm[];
    const int t = threadIdx.x;
    const int lane = t & 31, wid = t >> 5;
    const int bm = blockIdx.y, bn = blockIdx.x;
    const int warp_m = wid & 3, warp_n = wid >> 2;
    const uint32_t sb = smem_u32(sm);

    float c[2][8][4];
#pragma unroll
    for (int i = 0; i < 2; i++)
#pragma unroll
        for (int j = 0; j < 8; j++)
#pragma unroll
            for (int q = 0; q < 4; q++) c[i][j][q] = 0.f;

    const int nc = K / 64;
    const int row = t >> 3, seg = t & 7;           // not full coverage; loop p
    // issue loads for chunk kc into stage s
    auto issue = [&](int kc, int s) {
#pragma unroll
        for (int p = 0; p < 4; p++) {
            int u = t + p * 256;                   // 0..1023
            int r = u >> 3, sg = u & 7;
            uint32_t d = sb + s * STG + SWZ((uint32_t)(r * 128 + sg * 16));
            size_t ga = (size_t)(bm * 128 + r) * K + kc + sg * 8;
            size_t gb = (size_t)(bn * 128 + r) * K + kc + sg * 8;
            cp16(d,              g_a_hi + ga);
            cp16(d + 16384,      g_a_lo + ga);
            cp16(d + 32768,      g_bt_hi + gb);
            cp16(d + 49152,      g_bt_lo + gb);
        }
        CP_COMMIT();
    };
    (void)row; (void)seg;

    issue(0, 0);
    for (int ck = 0; ck < nc; ck++) {
        if (ck + 1 < nc) issue((ck + 1) * 64, (ck + 1) & 1);
        if (ck + 1 < nc) CP_WAIT1(); else CP_WAIT0();
        __syncthreads();

        const uint32_t stb = sb + (ck & 1) * STG;
        // per-thread ldmatrix source coords
        const int ar = (lane & 7) + ((lane >> 3) & 1) * 8;
        const int ak_off = (lane >= 16) ? 8 : 0;
        const int br = (lane & 7) + ((lane >= 16) ? 8 : 0);
        const int bk_off = ((lane >> 3) & 1) * 8;
#pragma unroll
        for (int ks = 0; ks < 4; ks++) {
            uint32_t a_hi[2][4], a_lo[2][4];
#pragma unroll
            for (int i = 0; i < 2; i++) {
                int m = warp_m * 32 + i * 16 + ar;
                int kk = ks * 16 + ak_off;
                uint32_t addr = stb + SWZ((uint32_t)(m * 128 + kk * 2));
                ldsm4(a_hi[i], addr);
                ldsm4(a_lo[i], addr + 16384);
            }
            uint32_t b_hi[8][2], b_lo[8][2];
#pragma unroll
            for (int jp = 0; jp < 4; jp++) {
                int n = warp_n * 64 + jp * 16 + br;
                int kk = ks * 16 + bk_off;
                uint32_t addr = stb + 32768 + SWZ((uint32_t)(n * 128 + kk * 2));
                uint32_t rh[4], rl[4];
                ldsm4(rh, addr);
                ldsm4(rl, addr + 16384);
                b_hi[2 * jp][0] = rh[0]; b_hi[2 * jp][1] = rh[1];
                b_hi[2 * jp + 1][0] = rh[2]; b_hi[2 * jp + 1][1] = rh[3];
                b_lo[2 * jp][0] = rl[0]; b_lo[2 * jp][1] = rl[1];
                b_lo[2 * jp + 1][0] = rl[2]; b_lo[2 * jp + 1][1] = rl[3];
            }
#pragma unroll
            for (int i = 0; i < 2; i++)
#pragma unroll
                for (int j = 0; j < 8; j++) {
                    mma16816(c[i][j], a_hi[i], b_hi[j]);
                    mma16816(c[i][j], a_hi[i], b_lo[j]);
                    mma16816(c[i][j], a_lo[i], b_hi[j]);
                }
        }
        __syncthreads();
    }

    // epilogue (rows < NNP: buffers padded, guard-free)
    const int g = lane >> 2, q = lane & 3;
#pragma unroll
    for (int i = 0; i < 2; i++) {
        int m0 = bm * 128 + warp_m * 32 + i * 16 + g;
#pragma unroll
        for (int j = 0; j < 8; j++) {
            int n = bn * 128 + warp_n * 64 + j * 8 + q * 2;
            *(float2*)(C + (size_t)m0 * Nc + n)       = make_float2(c[i][j][0], c[i][j][1]);
            *(float2*)(C + (size_t)(m0 + 8) * Nc + n) = make_float2(c[i][j][2], c[i][j][3]);
        }
    }
}

// ---------------- attention scores ----------------
__global__ __launch_bounds__(256) void k_att(
    const float* __restrict__ hx, const float* __restrict__ atts,
    const float* __restrict__ attd)
{
    int gt = blockIdx.x * blockDim.x + threadIdx.x;
    int w = gt >> 5, lane = gt & 31;
    if (w >= NN * HH) return;
    int n = w / HH, h = w - n * HH;
    const float* row = hx + (size_t)n * FD + h * CH;
    const float* vs = atts + h * CH;
    const float* vd = attd + h * CH;
    float sa = 0.f, sd = 0.f;
#pragma unroll
    for (int c = lane; c < CH; c += 32) {
        float v = row[c];
        sa += v * vs[c];
        sd += v * vd[c];
    }
#pragma unroll
    for (int o = 16; o; o >>= 1) {
        sa += __shfl_down_sync(0xffffffffu, sa, o);
        sd += __shfl_down_sync(0xffffffffu, sd, o);
    }
    if (lane == 0) { g_as[w] = sa; g_ad[w] = sd; }
}

// ---------------- fused softmax + aggregate + bias + relu ----------------
__global__ __launch_bounds__(256) void k_agg(
    const float* __restrict__ hx, const float* __restrict__ bias,
    float* __restrict__ out)
{
    int d = blockIdx.x;
    int t = threadIdx.x;
    __shared__ float    s_ad[HH];
    __shared__ unsigned s_m[HH];
    __shared__ float    s_mf[HH];
    __shared__ float    s_s[HH];
    __shared__ float    s_w[128 * HH];
    __shared__ int      s_src[128];

    int p0 = g_ptr[d], p1 = g_ptr[d + 1];
    int deg = p1 - p0;
    if (t < HH) {
        s_ad[t] = g_ad[d * HH + t];
        s_m[t] = ENC_NEG_INF;
        s_s[t] = 0.f;
    }
    __syncthreads();

    float lm[HH];
#pragma unroll
    for (int h = 0; h < HH; h++) lm[h] = -3.0e38f;
    for (int i = t; i < deg; i += 256) {
        int s = g_csr[p0 + i];
#pragma unroll
        for (int h = 0; h < HH; h++) {
            float e = g_as[s * HH + h] + s_ad[h];
            e = (e > 0.f) ? e : 0.2f * e;
            lm[h] = fmaxf(lm[h], e);
        }
    }
#pragma unroll
    for (int h = 0; h < HH; h++) atomicMax(&s_m[h], fenc(lm[h]));
    __syncthreads();
    if (t < HH) s_mf[t] = fdec(s_m[t]);
    __syncthreads();

    float a0 = 0.f, a1 = 0.f, a2 = 0.f;
    int c0 = t, c1 = t + 256, c2 = t + 512;
    int h0 = c0 >> 7, h1 = c1 >> 7, h2 = c2 >> 7;
    for (int cb = 0; cb < deg; cb += 128) {
        int cl = min(128, deg - cb);
        for (int j = t; j < cl * HH; j += 256) {
            int i = j / HH, h = j - i * HH;
            int s = g_csr[p0 + cb + i];
            if (h == 0) s_src[i] = s;
            float e = g_as[s * HH + h] + s_ad[h];
            e = (e > 0.f) ? e : 0.2f * e;
            float w = __expf(e - s_mf[h]);
            s_w[i * HH + h] = w;
            atomicAdd(&s_s[h], w);
        }
        __syncthreads();
        for (int i = 0; i < cl; i++) {
            const float* row = hx + (size_t)s_src[i] * FD;
            a0 += s_w[i * HH + h0] * row[c0];
            a1 += s_w[i * HH + h1] * row[c1];
            a2 += s_w[i * HH + h2] * row[c2];
        }
        __syncthreads();
    }

    float r0 = a0 / s_s[h0] + bias[c0];
    float r1 = a1 / s_s[h1] + bias[c1];
    float r2 = a2 / s_s[h2] + bias[c2];
    size_t base = (size_t)d * FD;
    out[base + c0] = fmaxf(r0, 0.f);
    out[base + c1] = fmaxf(r1, 0.f);
    out[base + c2] = fmaxf(r2, 0.f);
}

// ---------------- batch norm stats (apply fused into k_split) ----------------
__global__ void k_zero_cols() {
    int i = blockIdx.x * blockDim.x + threadIdx.x;
    if (i < FD) { g_colsum[i] = 0.f; g_colsum2[i] = 0.f; }
}

__global__ __launch_bounds__(256) void k_bn_stats(const float* __restrict__ y) {
    int b = blockIdx.x;
    int rows_per = (NN + gridDim.x - 1) / gridDim.x;
    int r0 = b * rows_per;
    int r1 = min(NN, r0 + rows_per);
    int t = threadIdx.x;
    float s[3] = {0.f, 0.f, 0.f}, q[3] = {0.f, 0.f, 0.f};
    for (int r = r0; r < r1; r++) {
        const float* row = y + (size_t)r * FD;
#pragma unroll
        for (int k = 0; k < 3; k++) {
            float v = row[t + k * 256];
            s[k] += v;
            q[k] += v * v;
        }
    }
#pragma unroll
    for (int k = 0; k < 3; k++) {
        atomicAdd(&g_colsum[t + k * 256], s[k]);
        atomicAdd(&g_colsum2[t + k * 256], q[k]);
    }
}

__global__ void k_bn_fin(const float* __restrict__ g, const float* __restrict__ be) {
    int c = blockIdx.x * blockDim.x + threadIdx.x;
    if (c >= FD) return;
    float mu = g_colsum[c] * (1.0f / NN);
    float var = g_colsum2[c] * (1.0f / NN) - mu * mu;
    float sc = g[c] * rsqrtf(var + 1e-5f);
    g_scale[c] = sc;
    g_shift[c] = be[c] - mu * sc;
}

// ---------------- global max pool (bias fused) ----------------
__global__ void k_pool_init(unsigned* __restrict__ out) {
    int i = blockIdx.x * blockDim.x + threadIdx.x;
    if (i < BGR * OC) out[i] = ENC_NEG_INF;
}

__global__ void k_pool(const int* __restrict__ ibatch, const float* __restrict__ lb,
                       unsigned* __restrict__ out) {
    int i = blockIdx.x * blockDim.x + threadIdx.x;
    if (i >= NN * OC) return;
    int n = i / OC, c = i - n * OC;
    int g = ibatch[n];
    atomicMax(&out[g * OC + c], fenc(g_lin[i] + lb[c]));
}

__global__ void k_pool_dec(float* __restrict__ out) {
    int i = blockIdx.x * blockDim.x + threadIdx.x;
    if (i < BGR * OC) {
        unsigned u = ((unsigned*)out)[i];
        out[i] = fdec(u);
    }
}

// ---------------- launch ----------------
extern "C" void kernel_launch(void* const* d_in, const int* in_sizes, int n_in,
                              void* d_out, int out_size) {
    const float* x   = (const float*)d_in[0];
    const int*   adj = (const int*)d_in[1];
    const int*   ib  = (const int*)d_in[2];
    const float* W1  = (const float*)d_in[3];
    const float* as1 = (const float*)d_in[4];
    const float* ad1 = (const float*)d_in[5];
    const float* b1  = (const float*)d_in[6];
    const float* g1  = (const float*)d_in[7];
    const float* be1 = (const float*)d_in[8];
    const float* W2  = (const float*)d_in[9];
    const float* as2 = (const float*)d_in[10];
    const float* ad2 = (const float*)d_in[11];
    const float* b2  = (const float*)d_in[12];
    const float* g2  = (const float*)d_in[13];
    const float* be2 = (const float*)d_in[14];
    const float* lW  = (const float*)d_in[15];
    const float* lb  = (const float*)d_in[16];

    float *hx, *y, *lin, *scale, *shift;
    cudaGetSymbolAddress((void**)&hx, g_hx);
    cudaGetSymbolAddress((void**)&y, g_y);
    cudaGetSymbolAddress((void**)&lin, g_lin);
    cudaGetSymbolAddress((void**)&scale, g_scale);
    cudaGetSymbolAddress((void**)&shift, g_shift);

    static bool attr_set = false;
    if (!attr_set) {
        cudaFuncSetAttribute(k_gemm_mma, cudaFuncAttributeMaxDynamicSharedMemorySize, SM_GEMM);
        attr_set = true;
    }

    // CSR build
    k_zero_deg<<<(NN + 255) / 256, 256>>>();
    k_count<<<(NET + 255) / 256, 256>>>(adj);
    k_scan<<<1, 1024>>>();
    k_scatter<<<(NET + 255) / 256, 256>>>(adj);

    dim3 tp(32, 8);
    dim3 gemm_grid(FD / 128, NNP / 128);
    dim3 lin_grid(OC / 128, NNP / 128);

    // layer 1: hx = x @ W1
    k_prep_w<<<dim3(FD / 32, 256 / 32), tp>>>(W1, 256, FD);
    k_split<<<(NNP * 64 + 255) / 256, 256>>>(x, nullptr, nullptr, 256);
    k_gemm_mma<<<gemm_grid, 256, SM_GEMM>>>(hx, FD, 256);
    k_att<<<(NN * HH * 32 + 255) / 256, 256>>>(hx, as1, ad1);
    k_agg<<<NN, 256>>>(hx, b1, y);
    k_zero_cols<<<3, 256>>>();
    k_bn_stats<<<80, 256>>>(y);
    k_bn_fin<<<3, 256>>>(g1, be1);

    // layer 2: hx = BN1(y) @ W2 (BN fused into split)
    k_prep_w<<<dim3(FD / 32, FD / 32), tp>>>(W2, FD, FD);
    k_split<<<(NNP * 192 + 255) / 256, 256>>>(y, scale, shift, FD);
    k_gemm_mma<<<gemm_grid, 256, SM_GEMM>>>(hx, FD, FD);
    k_att<<<(NN * HH * 32 + 255) / 256, 256>>>(hx, as2, ad2);
    k_agg<<<NN, 256>>>(hx, b2, y);
    k_zero_cols<<<3, 256>>>();
    k_bn_stats<<<80, 256>>>(y);
    k_bn_fin<<<3, 256>>>(g2, be2);

    // linear head: lin = BN2(y) @ lW
    k_prep_w<<<dim3(OC / 32, FD / 32), tp>>>(lW, FD, OC);
    k_split<<<(NNP * 192 + 255) / 256, 256>>>(y, scale, shift, FD);
    k_gemm_mma<<<lin_grid, 256, SM_GEMM>>>(lin, OC, FD);

    // pooling (lin bias fused)
    k_pool_init<<<(BGR * OC + 255) / 256, 256>>>((unsigned*)d_out);
    k_pool<<<(NN * OC + 255) / 256, 256>>>(ib, lb, (unsigned*)d_out);
    k_pool_dec<<<(BGR * OC + 255) / 256, 256>>>((float*)d_out);
}